// round 5
// baseline (speedup 1.0000x reference)
#include <cuda_runtime.h>
#include <cuda_fp16.h>
#include <math.h>
#include <stdint.h>

#define N_NODES 50000
#define HID 128
#define NODE_DIM 64
#define GRAPH_DIM 32
#define E_MAX 1700000

// ---------------- scratch (static device globals; no allocation) ----------------
__device__ float  g_hA[N_NODES * HID];
__device__ float  g_hB[N_NODES * HID];
__device__ __half g_fsh[N_NODES * HID];
__device__ float  g_fd[N_NODES * HID];
__device__ int    g_deg[N_NODES];
__device__ int    g_off[N_NODES + 1];
__device__ int    g_cur[N_NODES];
__device__ int    g_csrc[E_MAX];
__device__ float  g_pool[HID];
__device__ float  g_emb_scratch[HID];

// ---------------- CSR build ----------------
__global__ void zero_kernel() {
    int i = blockIdx.x * blockDim.x + threadIdx.x;
    if (i < N_NODES) g_deg[i] = 0;
    if (i < HID) g_pool[i] = 0.f;
}

__global__ void count_kernel(const int* __restrict__ dst, int E) {
    int e = blockIdx.x * blockDim.x + threadIdx.x;
    if (e < E) atomicAdd(&g_deg[dst[e]], 1);
}

__global__ void scan_kernel() {
    __shared__ int sums[1024];
    const int CH = (N_NODES + 1023) / 1024;
    int t = threadIdx.x;
    int st = t * CH;
    int en = st + CH; if (en > N_NODES) en = N_NODES;
    if (st > N_NODES) st = N_NODES;
    int s = 0;
    for (int i = st; i < en; i++) s += g_deg[i];
    sums[t] = s;
    __syncthreads();
    for (int d = 1; d < 1024; d <<= 1) {
        int v = (t >= d) ? sums[t - d] : 0;
        __syncthreads();
        sums[t] += v;
        __syncthreads();
    }
    int run = (t == 0) ? 0 : sums[t - 1];
    for (int i = st; i < en; i++) {
        g_off[i] = run;
        g_cur[i] = run;
        run += g_deg[i];
    }
    if (t == 1023) g_off[N_NODES] = sums[1023];
}

__global__ void scatter_kernel(const int* __restrict__ src, const int* __restrict__ dst, int E) {
    int e = blockIdx.x * blockDim.x + threadIdx.x;
    if (e < E) {
        int d = dst[e];
        int pos = atomicAdd(&g_cur[d], 1);
        g_csrc[pos] = src[e];
    }
}

// ---------------- tf32 tensor-core GEMM ----------------
__device__ __forceinline__ uint32_t f2tf(float f) {
    uint32_t u;
    asm("cvt.rna.tf32.f32 %0, %1;" : "=r"(u) : "f"(f));
    return u;
}

__device__ __forceinline__ void mma_tf32(float* c, const uint32_t* a, const uint32_t* b) {
    asm volatile(
        "mma.sync.aligned.m16n8k8.row.col.f32.tf32.tf32.f32 "
        "{%0,%1,%2,%3}, {%4,%5,%6,%7}, {%8,%9}, {%0,%1,%2,%3};"
        : "+f"(c[0]), "+f"(c[1]), "+f"(c[2]), "+f"(c[3])
        : "r"(a[0]), "r"(a[1]), "r"(a[2]), "r"(a[3]), "r"(b[0]), "r"(b[1]));
}

// HALF1: blockIdx.y==0 output written as __half to C1h; else fp32 to C2.
template <int K, bool HALF1>
__global__ void __launch_bounds__(256) gemm_tc_kernel(
    const float* __restrict__ A,
    const float* __restrict__ W1, const float* __restrict__ b1, void* __restrict__ C1v,
    const float* __restrict__ W2, const float* __restrict__ b2, float* __restrict__ C2)
{
    constexpr int KP = K + 8;
    constexpr int BKP = K + 8;
    extern __shared__ uint32_t smem_u[];
    uint32_t* sA = smem_u;
    uint32_t* sB = smem_u + 128 * KP;

    const float* W; const float* bias;
    bool halfOut = HALF1 && (blockIdx.y == 0);
    if (blockIdx.y == 0) { W = W1; bias = b1; }
    else                 { W = W2; bias = b2; }

    int row0 = blockIdx.x * 128;
    int tid = threadIdx.x;

    for (int i = tid; i < 128 * (K / 4); i += 256) {
        int r = i / (K / 4);
        int q = i % (K / 4);
        int row = row0 + r;
        float4 v = make_float4(0.f, 0.f, 0.f, 0.f);
        if (row < N_NODES) v = *(const float4*)(A + (size_t)row * K + q * 4);
        int base = r * KP + (q >> 1) * 8;
        int lo = q & 1;
        sA[base + 0 + lo] = f2tf(v.x);
        sA[base + 2 + lo] = f2tf(v.y);
        sA[base + 4 + lo] = f2tf(v.z);
        sA[base + 6 + lo] = f2tf(v.w);
    }
    for (int i = tid; i < K * 32; i += 256) {
        int k = i >> 5;
        int c4 = i & 31;
        float4 v = *(const float4*)(W + (size_t)k * HID + c4 * 4);
        int off = (k >> 3) * 8 + (k & 3) * 2 + ((k >> 2) & 1);
        int n = c4 * 4;
        sB[(n + 0) * BKP + off] = f2tf(v.x);
        sB[(n + 1) * BKP + off] = f2tf(v.y);
        sB[(n + 2) * BKP + off] = f2tf(v.z);
        sB[(n + 3) * BKP + off] = f2tf(v.w);
    }
    __syncthreads();

    int warp = tid >> 5;
    int lane = tid & 31;
    int mwarp = warp >> 1;
    int nwarp = warp & 1;
    int g = lane >> 2;
    int tg = lane & 3;

    float acc[2][8][4];
#pragma unroll
    for (int t = 0; t < 2; t++)
#pragma unroll
        for (int j = 0; j < 8; j++) { acc[t][j][0] = acc[t][j][1] = acc[t][j][2] = acc[t][j][3] = 0.f; }

    int rb = mwarp * 32 + g;
#pragma unroll
    for (int ks = 0; ks < K / 8; ks++) {
        int kk = ks * 8 + tg * 2;
        uint2 a00 = *(const uint2*)(sA + (rb)      * KP + kk);
        uint2 a01 = *(const uint2*)(sA + (rb + 8)  * KP + kk);
        uint2 a10 = *(const uint2*)(sA + (rb + 16) * KP + kk);
        uint2 a11 = *(const uint2*)(sA + (rb + 24) * KP + kk);
        uint32_t afr0[4] = {a00.x, a01.x, a00.y, a01.y};
        uint32_t afr1[4] = {a10.x, a11.x, a10.y, a11.y};
        uint32_t bfr[8][2];
#pragma unroll
        for (int j = 0; j < 8; j++) {
            int n0 = nwarp * 64 + j * 8 + g;
            uint2 b = *(const uint2*)(sB + n0 * BKP + kk);
            bfr[j][0] = b.x; bfr[j][1] = b.y;
        }
#pragma unroll
        for (int j = 0; j < 8; j++) mma_tf32(acc[0][j], afr0, bfr[j]);
#pragma unroll
        for (int j = 0; j < 8; j++) mma_tf32(acc[1][j], afr1, bfr[j]);
    }

#pragma unroll
    for (int t = 0; t < 2; t++) {
        int rbase = row0 + mwarp * 32 + t * 16 + g;
#pragma unroll
        for (int j = 0; j < 8; j++) {
            int col = nwarp * 64 + j * 8 + tg * 2;
            float bx = __ldg(bias + col);
            float by = __ldg(bias + col + 1);
            float v0x = acc[t][j][0] + bx, v0y = acc[t][j][1] + by;
            float v1x = acc[t][j][2] + bx, v1y = acc[t][j][3] + by;
            if (halfOut) {
                __half* C = (__half*)C1v;
                if (rbase < N_NODES)
                    *(__half2*)(C + (size_t)rbase * HID + col) = __floats2half2_rn(v0x, v0y);
                if (rbase + 8 < N_NODES)
                    *(__half2*)(C + (size_t)(rbase + 8) * HID + col) = __floats2half2_rn(v1x, v1y);
            } else {
                float* C = (blockIdx.y == 0) ? (float*)C1v : C2;
                if (rbase < N_NODES)
                    *(float2*)(C + (size_t)rbase * HID + col) = make_float2(v0x, v0y);
                if (rbase + 8 < N_NODES)
                    *(float2*)(C + (size_t)(rbase + 8) * HID + col) = make_float2(v1x, v1y);
            }
        }
    }
}

// ---------------- GATv2 layer: warp/node, fp16 fs gather, depth-4 prefetch ----------------
__device__ __forceinline__ float4 h4_to_f4(uint2 q) {
    float2 lo = __half22float2(*(__half2*)&q.x);
    float2 hi = __half22float2(*(__half2*)&q.y);
    return make_float4(lo.x, lo.y, hi.x, hi.y);
}

__global__ void __launch_bounds__(256) gat_layer_kernel(
    const __half* __restrict__ fsh, const float* __restrict__ fd,
    const float* __restrict__ h_in, const float* __restrict__ attn,
    const float* __restrict__ lng, const float* __restrict__ lnb,
    float* __restrict__ h_out)
{
    int warp = (blockIdx.x * blockDim.x + threadIdx.x) >> 5;
    if (warp >= N_NODES) return;
    int node = warp;
    int lane = threadIdx.x & 31;
    int c = lane * 4;

    const float4 fd4 = *(const float4*)(fd + (size_t)node * HID + c);
    const float4 h4  = *(const float4*)(h_in + (size_t)node * HID + c);
    const float4 a4  = *(const float4*)(attn + c);

    int p0 = g_off[node];
    int n  = g_off[node + 1] - p0;   // >= 1 (self-loop)

    float ssum = 0.f;
    float4 acc = make_float4(0.f, 0.f, 0.f, 0.f);

    uint2 q0 = make_uint2(0u, 0u), q1 = q0, q2 = q0, q3 = q0;
    q0 = *(const uint2*)(fsh + (size_t)g_csrc[p0] * HID + c);
    if (n > 1) q1 = *(const uint2*)(fsh + (size_t)g_csrc[p0 + 1] * HID + c);
    if (n > 2) q2 = *(const uint2*)(fsh + (size_t)g_csrc[p0 + 2] * HID + c);
    if (n > 3) q3 = *(const uint2*)(fsh + (size_t)g_csrc[p0 + 3] * HID + c);

    int i = 0;
    for (; i + 1 < n; i += 2) {
        float4 f0 = h4_to_f4(q0);
        float4 f1 = h4_to_f4(q1);
        q0 = q2; q1 = q3;
        if (i + 4 < n) q2 = *(const uint2*)(fsh + (size_t)g_csrc[p0 + i + 4] * HID + c);
        if (i + 5 < n) q3 = *(const uint2*)(fsh + (size_t)g_csrc[p0 + i + 5] * HID + c);

        float t0, t1;
        t0 = f0.x + fd4.x; t0 = t0 > 0.f ? t0 : 0.2f * t0;
        t1 = f1.x + fd4.x; t1 = t1 > 0.f ? t1 : 0.2f * t1;
        float pd0 = t0 * a4.x, pd1 = t1 * a4.x;
        t0 = f0.y + fd4.y; t0 = t0 > 0.f ? t0 : 0.2f * t0;
        t1 = f1.y + fd4.y; t1 = t1 > 0.f ? t1 : 0.2f * t1;
        pd0 += t0 * a4.y; pd1 += t1 * a4.y;
        t0 = f0.z + fd4.z; t0 = t0 > 0.f ? t0 : 0.2f * t0;
        t1 = f1.z + fd4.z; t1 = t1 > 0.f ? t1 : 0.2f * t1;
        pd0 += t0 * a4.z; pd1 += t1 * a4.z;
        t0 = f0.w + fd4.w; t0 = t0 > 0.f ? t0 : 0.2f * t0;
        t1 = f1.w + fd4.w; t1 = t1 > 0.f ? t1 : 0.2f * t1;
        pd0 += t0 * a4.w; pd1 += t1 * a4.w;

        pd0 += __shfl_xor_sync(0xffffffffu, pd0, 1);
        pd1 += __shfl_xor_sync(0xffffffffu, pd1, 1);
        pd0 += __shfl_xor_sync(0xffffffffu, pd0, 2);
        pd1 += __shfl_xor_sync(0xffffffffu, pd1, 2);
        pd0 += __shfl_xor_sync(0xffffffffu, pd0, 4);
        pd1 += __shfl_xor_sync(0xffffffffu, pd1, 4);

        float w0 = __expf(pd0);
        float w1 = __expf(pd1);
        ssum += w0 + w1;
        acc.x += w0 * f0.x + w1 * f1.x;
        acc.y += w0 * f0.y + w1 * f1.y;
        acc.z += w0 * f0.z + w1 * f1.z;
        acc.w += w0 * f0.w + w1 * f1.w;
    }
    if (i < n) {
        float4 f = h4_to_f4(q0);
        float t;
        t = f.x + fd4.x; t = t > 0.f ? t : 0.2f * t; float pd = t * a4.x;
        t = f.y + fd4.y; t = t > 0.f ? t : 0.2f * t; pd += t * a4.y;
        t = f.z + fd4.z; t = t > 0.f ? t : 0.2f * t; pd += t * a4.z;
        t = f.w + fd4.w; t = t > 0.f ? t : 0.2f * t; pd += t * a4.w;
        pd += __shfl_xor_sync(0xffffffffu, pd, 1);
        pd += __shfl_xor_sync(0xffffffffu, pd, 2);
        pd += __shfl_xor_sync(0xffffffffu, pd, 4);
        float w = __expf(pd);
        ssum += w;
        acc.x += w * f.x; acc.y += w * f.y; acc.z += w * f.z; acc.w += w * f.w;
    }

    float inv = 1.f / ssum;
    float x0 = acc.x * inv + 2.f * h4.x;
    float x1 = acc.y * inv + 2.f * h4.y;
    float x2 = acc.z * inv + 2.f * h4.z;
    float x3 = acc.w * inv + 2.f * h4.w;
    float s1 = x0 + x1 + x2 + x3;
#pragma unroll
    for (int d = 16; d; d >>= 1) s1 += __shfl_xor_sync(0xffffffffu, s1, d);
    float mean = s1 * (1.f / 128.f);
    float d0 = x0 - mean, d1 = x1 - mean, d2 = x2 - mean, d3 = x3 - mean;
    float s2 = d0 * d0 + d1 * d1 + d2 * d2 + d3 * d3;
#pragma unroll
    for (int d = 16; d; d >>= 1) s2 += __shfl_xor_sync(0xffffffffu, s2, d);
    float rstd = rsqrtf(s2 * (1.f / 128.f) + 1e-5f);
    float4 g4 = *(const float4*)(lng + c);
    float4 b4 = *(const float4*)(lnb + c);
    float y0 = fmaxf(d0 * rstd * g4.x + b4.x, 0.f);
    float y1 = fmaxf(d1 * rstd * g4.y + b4.y, 0.f);
    float y2 = fmaxf(d2 * rstd * g4.z + b4.z, 0.f);
    float y3 = fmaxf(d3 * rstd * g4.w + b4.w, 0.f);
    *(float4*)(h_out + (size_t)node * HID + c) = make_float4(y0, y1, y2, y3);
}

// ---------------- mean pool over nodes ----------------
__global__ void pool_kernel(const float* __restrict__ h) {
    int col = threadIdx.x;
    int r0 = blockIdx.x * 512;
    int r1 = r0 + 512; if (r1 > N_NODES) r1 = N_NODES;
    float s = 0.f;
    for (int r = r0; r < r1; r++) s += h[(size_t)r * HID + col];
    atomicAdd(&g_pool[col], s);
}

// ---------------- graph head ----------------
__global__ void head_kernel(
    const float* __restrict__ gf, const float* __restrict__ W_g, const float* __restrict__ b_g,
    const float* __restrict__ W_f1, const float* __restrict__ b_f1,
    const float* __restrict__ W_f2, const float* __restrict__ b_f2,
    float* __restrict__ emb)
{
    __shared__ float comb[256];
    __shared__ float r1[128];
    int t = threadIdx.x;
    float gh = b_g[t];
    for (int k = 0; k < GRAPH_DIM; k++) gh += gf[k] * W_g[k * HID + t];
    comb[128 + t] = gh;
    comb[t] = g_pool[t] * (1.f / (float)N_NODES);
    __syncthreads();
    float f1 = b_f1[t];
    for (int k = 0; k < 256; k++) f1 += comb[k] * W_f1[k * HID + t];
    r1[t] = fmaxf(f1, 0.f);
    __syncthreads();
    float f2 = b_f2[t];
    for (int k = 0; k < 128; k++) f2 += r1[k] * W_f2[k * HID + t];
    emb[t] = f2;
}

// ---------------- launch ----------------
extern "C" void kernel_launch(void* const* d_in, const int* in_sizes, int n_in,
                              void* d_out, int out_size)
{
    const float* node_feats  = (const float*)d_in[0];
    const float* graph_feats = (const float*)d_in[1];
    const int*   src         = (const int*)d_in[2];
    const int*   dst         = (const int*)d_in[3];
    const float* W_in  = (const float*)d_in[4];
    const float* b_in  = (const float*)d_in[5];
    const float* W_g   = (const float*)d_in[6];
    const float* b_g   = (const float*)d_in[7];
    const float* W_src = (const float*)d_in[8];
    const float* b_src = (const float*)d_in[9];
    const float* W_dst = (const float*)d_in[10];
    const float* b_dst = (const float*)d_in[11];
    const float* attn  = (const float*)d_in[12];
    const float* ln_g  = (const float*)d_in[13];
    const float* ln_b  = (const float*)d_in[14];
    const float* W_f1  = (const float*)d_in[15];
    const float* b_f1  = (const float*)d_in[16];
    const float* W_f2  = (const float*)d_in[17];
    const float* b_f2  = (const float*)d_in[18];

    int E = in_sizes[2];
    if (E > E_MAX) E = E_MAX;

    float *hA, *hB, *fd, *embS;
    __half* fsh;
    cudaGetSymbolAddress((void**)&hA,   g_hA);
    cudaGetSymbolAddress((void**)&hB,   g_hB);
    cudaGetSymbolAddress((void**)&fsh,  g_fsh);
    cudaGetSymbolAddress((void**)&fd,   g_fd);
    cudaGetSymbolAddress((void**)&embS, g_emb_scratch);

    float* out = (float*)d_out;
    float* emb_dst;
    float* hfin;
    long long need = (long long)HID + (long long)N_NODES * HID;
    if ((long long)out_size >= need)            { emb_dst = out;  hfin = out + HID; }
    else if (out_size == N_NODES * HID)         { emb_dst = embS; hfin = out; }
    else                                        { emb_dst = out;  hfin = hB; }

    const int smem128 = (128 * (128 + 8) + 128 * (128 + 8)) * 4;  // 139264 B
    const int smem64  = (128 * (64 + 8)  + 128 * (64 + 8))  * 4;  // 73728 B

    static cudaStream_t s2 = nullptr;
    static cudaEvent_t evFork = nullptr, evJoin = nullptr;
    static bool init_done = false;
    if (!init_done) {
        cudaFuncSetAttribute(gemm_tc_kernel<128, true>, cudaFuncAttributeMaxDynamicSharedMemorySize, smem128);
        cudaFuncSetAttribute(gemm_tc_kernel<64, false>, cudaFuncAttributeMaxDynamicSharedMemorySize, smem64);
        cudaStreamCreateWithFlags(&s2, cudaStreamNonBlocking);
        cudaEventCreateWithFlags(&evFork, cudaEventDisableTiming);
        cudaEventCreateWithFlags(&evJoin, cudaEventDisableTiming);
        init_done = true;
    }

    // Fork: CSR build on s2, concurrent with input projection + layer-0 GEMMs
    cudaEventRecord(evFork, 0);
    cudaStreamWaitEvent(s2, evFork, 0);
    zero_kernel<<<(N_NODES + 255) / 256, 256, 0, s2>>>();
    count_kernel<<<(E + 255) / 256, 256, 0, s2>>>(dst, E);
    scan_kernel<<<1, 1024, 0, s2>>>();
    scatter_kernel<<<(E + 255) / 256, 256, 0, s2>>>(src, dst, E);
    cudaEventRecord(evJoin, s2);

    // Main stream: input projection (tensor core, fp32 out)
    {
        dim3 grid((N_NODES + 127) / 128, 1);
        gemm_tc_kernel<64, false><<<grid, 256, smem64>>>(node_feats, W_in, b_in, (void*)hA, W_in, b_in, hA);
    }

    float* hin = hA;
    for (int l = 0; l < 3; l++) {
        dim3 grid((N_NODES + 127) / 128, 2);
        gemm_tc_kernel<128, true><<<grid, 256, smem128>>>(
            hin,
            W_src + (size_t)l * HID * HID, b_src + (size_t)l * HID, (void*)fsh,
            W_dst + (size_t)l * HID * HID, b_dst + (size_t)l * HID, fd);
        if (l == 0) cudaStreamWaitEvent(0, evJoin, 0);   // join CSR before first gat
        float* hout = (l == 2) ? hfin : ((hin == hA) ? hB : hA);
        gat_layer_kernel<<<(N_NODES + 7) / 8, 256>>>(
            fsh, fd, hin, attn + (size_t)l * HID,
            ln_g + (size_t)l * HID, ln_b + (size_t)l * HID, hout);
        hin = hout;
    }

    pool_kernel<<<(N_NODES + 511) / 512, 128>>>(hin);
    head_kernel<<<1, 128>>>(graph_feats, W_g, b_g, W_f1, b_f1, W_f2, b_f2, emb_dst);
}

// round 6
// speedup vs baseline: 1.3258x; 1.3258x over previous
#include <cuda_runtime.h>
#include <cuda_fp16.h>
#include <math.h>
#include <stdint.h>

#define N_NODES 50000
#define HID 128
#define NODE_DIM 64
#define GRAPH_DIM 32
#define E_MAX 1700000

// ---------------- scratch (static device globals; no allocation) ----------------
__device__ float  g_hA[N_NODES * HID];
__device__ float  g_hB[N_NODES * HID];
__device__ __half g_fsh[N_NODES * HID];
__device__ float  g_fd[N_NODES * HID];
__device__ int    g_deg[N_NODES];
__device__ int    g_off[N_NODES + 1];
__device__ int    g_cur[N_NODES];
__device__ int    g_csrc[E_MAX];
__device__ float  g_pool[HID];
__device__ float  g_emb_scratch[HID];
// prepped fp16 weights, permuted fragment layout. KP2(HID)=72 words/row, KP2(64)=40.
__device__ uint4  g_Whs[3][128 * 72 / 4];
__device__ uint4  g_Whd[3][128 * 72 / 4];
__device__ uint4  g_Whin[128 * 40 / 4];

// ---------------- CSR build ----------------
__global__ void zero_kernel() {
    int i = blockIdx.x * blockDim.x + threadIdx.x;
    if (i < N_NODES) g_deg[i] = 0;
    if (i < HID) g_pool[i] = 0.f;
}

__global__ void count_kernel(const int* __restrict__ dst, int E) {
    int e = blockIdx.x * blockDim.x + threadIdx.x;
    if (e < E) atomicAdd(&g_deg[dst[e]], 1);
}

__global__ void scan_kernel() {
    __shared__ int sums[1024];
    const int CH = (N_NODES + 1023) / 1024;
    int t = threadIdx.x;
    int st = t * CH;
    int en = st + CH; if (en > N_NODES) en = N_NODES;
    if (st > N_NODES) st = N_NODES;
    int s = 0;
    for (int i = st; i < en; i++) s += g_deg[i];
    sums[t] = s;
    __syncthreads();
    for (int d = 1; d < 1024; d <<= 1) {
        int v = (t >= d) ? sums[t - d] : 0;
        __syncthreads();
        sums[t] += v;
        __syncthreads();
    }
    int run = (t == 0) ? 0 : sums[t - 1];
    for (int i = st; i < en; i++) {
        g_off[i] = run;
        g_cur[i] = run;
        run += g_deg[i];
    }
    if (t == 1023) g_off[N_NODES] = sums[1023];
}

__global__ void scatter_kernel(const int* __restrict__ src, const int* __restrict__ dst, int E) {
    int e = blockIdx.x * blockDim.x + threadIdx.x;
    if (e < E) {
        int d = dst[e];
        int pos = atomicAdd(&g_cur[d], 1);
        g_csrc[pos] = src[e];
    }
}

// ---------------- weight prep: fp32 [K][128] -> permuted fp16 frag layout ----------------
// word layout: out[n*KP2 + (k>>4)*8 + o(u)], u=(k&15)>>1, o(u)=(u&3)*2+(u>>2), half2 = (k, k+1)
__global__ void prep_w_kernel(const float* __restrict__ W, uint32_t* __restrict__ out, int K) {
    int idx = blockIdx.x * blockDim.x + threadIdx.x;
    int half_k = K >> 1;
    if (idx >= 128 * half_k) return;
    int n = idx / half_k;
    int u_glob = idx % half_k;
    int k = u_glob * 2;
    float x = W[(size_t)k * HID + n];
    float y = W[(size_t)(k + 1) * HID + n];
    int KP2 = half_k + 8;
    int uu = (k & 15) >> 1;
    int o = (uu & 3) * 2 + (uu >> 2);
    __half2 h = __floats2half2_rn(x, y);
    out[n * KP2 + (k >> 4) * 8 + o] = *(uint32_t*)&h;
}

// ---------------- fp16 tensor-core GEMM (m16n8k16, fp32 accum) ----------------
__device__ __forceinline__ void mma_f16(float* c, const uint32_t* a, const uint32_t* b) {
    asm volatile(
        "mma.sync.aligned.m16n8k16.row.col.f32.f16.f16.f32 "
        "{%0,%1,%2,%3}, {%4,%5,%6,%7}, {%8,%9}, {%0,%1,%2,%3};"
        : "+f"(c[0]), "+f"(c[1]), "+f"(c[2]), "+f"(c[3])
        : "r"(a[0]), "r"(a[1]), "r"(a[2]), "r"(a[3]), "r"(b[0]), "r"(b[1]));
}

// HALF1: blockIdx.y==0 output written as __half to C1v; else fp32.
template <int K, bool HALF1>
__global__ void __launch_bounds__(256) gemm_tc_kernel(
    const float* __restrict__ A,
    const uint4* __restrict__ Wh1, const float* __restrict__ b1, void* __restrict__ C1v,
    const uint4* __restrict__ Wh2, const float* __restrict__ b2, float* __restrict__ C2)
{
    constexpr int KP2 = K / 2 + 8;          // words per row, == 8 mod 32
    extern __shared__ uint32_t smem_u[];
    uint32_t* sA = smem_u;                  // [128][KP2]
    uint32_t* sB = smem_u + 128 * KP2;      // [128 n][KP2]

    const uint4* Wh; const float* bias;
    bool halfOut = HALF1 && (blockIdx.y == 0);
    if (blockIdx.y == 0) { Wh = Wh1; bias = b1; }
    else                 { Wh = Wh2; bias = b2; }

    int row0 = blockIdx.x * 128;
    int tid = threadIdx.x;

    // A tile: convert fp32 -> permuted fp16 layout
    const int o0tab[4] = {0, 4, 1, 5};
    const int o1tab[4] = {2, 6, 3, 7};
    for (int i = tid; i < 128 * (K / 4); i += 256) {
        int r = i / (K / 4);
        int q = i % (K / 4);
        int row = row0 + r;
        float4 v = make_float4(0.f, 0.f, 0.f, 0.f);
        if (row < N_NODES) v = *(const float4*)(A + (size_t)row * K + q * 4);
        int base = r * KP2 + (q >> 2) * 8;
        __half2 h01 = __floats2half2_rn(v.x, v.y);
        __half2 h23 = __floats2half2_rn(v.z, v.w);
        sA[base + o0tab[q & 3]] = *(uint32_t*)&h01;
        sA[base + o1tab[q & 3]] = *(uint32_t*)&h23;
    }
    // B tile: straight copy of prepped weights
    {
        uint4* dst = (uint4*)sB;
        for (int i = tid; i < 128 * KP2 / 4; i += 256) dst[i] = Wh[i];
    }
    __syncthreads();

    int warp = tid >> 5;
    int lane = tid & 31;
    int mwarp = warp >> 1;
    int nwarp = warp & 1;
    int g = lane >> 2;
    int tg = lane & 3;

    float acc[2][8][4];
#pragma unroll
    for (int t = 0; t < 2; t++)
#pragma unroll
        for (int j = 0; j < 8; j++) { acc[t][j][0] = acc[t][j][1] = acc[t][j][2] = acc[t][j][3] = 0.f; }

    int rb = mwarp * 32 + g;
#pragma unroll
    for (int ks = 0; ks < K / 16; ks++) {
        int kk = ks * 8 + tg * 2;
        uint2 a00 = *(const uint2*)(sA + (rb)      * KP2 + kk);
        uint2 a01 = *(const uint2*)(sA + (rb + 8)  * KP2 + kk);
        uint2 a10 = *(const uint2*)(sA + (rb + 16) * KP2 + kk);
        uint2 a11 = *(const uint2*)(sA + (rb + 24) * KP2 + kk);
        uint32_t afr0[4] = {a00.x, a01.x, a00.y, a01.y};
        uint32_t afr1[4] = {a10.x, a11.x, a10.y, a11.y};
        uint32_t bfr[8][2];
#pragma unroll
        for (int j = 0; j < 8; j++) {
            int n0 = nwarp * 64 + j * 8 + g;
            uint2 b = *(const uint2*)(sB + n0 * KP2 + kk);
            bfr[j][0] = b.x; bfr[j][1] = b.y;
        }
#pragma unroll
        for (int j = 0; j < 8; j++) mma_f16(acc[0][j], afr0, bfr[j]);
#pragma unroll
        for (int j = 0; j < 8; j++) mma_f16(acc[1][j], afr1, bfr[j]);
    }

#pragma unroll
    for (int t = 0; t < 2; t++) {
        int rbase = row0 + mwarp * 32 + t * 16 + g;
#pragma unroll
        for (int j = 0; j < 8; j++) {
            int col = nwarp * 64 + j * 8 + tg * 2;
            float bx = __ldg(bias + col);
            float by = __ldg(bias + col + 1);
            float v0x = acc[t][j][0] + bx, v0y = acc[t][j][1] + by;
            float v1x = acc[t][j][2] + bx, v1y = acc[t][j][3] + by;
            if (halfOut) {
                __half* C = (__half*)C1v;
                if (rbase < N_NODES)
                    *(__half2*)(C + (size_t)rbase * HID + col) = __floats2half2_rn(v0x, v0y);
                if (rbase + 8 < N_NODES)
                    *(__half2*)(C + (size_t)(rbase + 8) * HID + col) = __floats2half2_rn(v1x, v1y);
            } else {
                float* C = (blockIdx.y == 0) ? (float*)C1v : C2;
                if (rbase < N_NODES)
                    *(float2*)(C + (size_t)rbase * HID + col) = make_float2(v0x, v0y);
                if (rbase + 8 < N_NODES)
                    *(float2*)(C + (size_t)(rbase + 8) * HID + col) = make_float2(v1x, v1y);
            }
        }
    }
}

// ---------------- GATv2 layer: warp/node, fp16 fs gather, depth-4 prefetch ----------------
__device__ __forceinline__ float4 h4_to_f4(uint2 q) {
    float2 lo = __half22float2(*(__half2*)&q.x);
    float2 hi = __half22float2(*(__half2*)&q.y);
    return make_float4(lo.x, lo.y, hi.x, hi.y);
}

__global__ void __launch_bounds__(256) gat_layer_kernel(
    const __half* __restrict__ fsh, const float* __restrict__ fd,
    const float* __restrict__ h_in, const float* __restrict__ attn,
    const float* __restrict__ lng, const float* __restrict__ lnb,
    float* __restrict__ h_out)
{
    int warp = (blockIdx.x * blockDim.x + threadIdx.x) >> 5;
    if (warp >= N_NODES) return;
    int node = warp;
    int lane = threadIdx.x & 31;
    int c = lane * 4;

    const float4 fd4 = *(const float4*)(fd + (size_t)node * HID + c);
    const float4 h4  = *(const float4*)(h_in + (size_t)node * HID + c);
    const float4 a4  = *(const float4*)(attn + c);

    int p0 = g_off[node];
    int n  = g_off[node + 1] - p0;   // >= 1 (self-loop)

    float ssum = 0.f;
    float4 acc = make_float4(0.f, 0.f, 0.f, 0.f);

    uint2 q0 = make_uint2(0u, 0u), q1 = q0, q2 = q0, q3 = q0;
    q0 = *(const uint2*)(fsh + (size_t)g_csrc[p0] * HID + c);
    if (n > 1) q1 = *(const uint2*)(fsh + (size_t)g_csrc[p0 + 1] * HID + c);
    if (n > 2) q2 = *(const uint2*)(fsh + (size_t)g_csrc[p0 + 2] * HID + c);
    if (n > 3) q3 = *(const uint2*)(fsh + (size_t)g_csrc[p0 + 3] * HID + c);

    int i = 0;
    for (; i + 1 < n; i += 2) {
        float4 f0 = h4_to_f4(q0);
        float4 f1 = h4_to_f4(q1);
        q0 = q2; q1 = q3;
        if (i + 4 < n) q2 = *(const uint2*)(fsh + (size_t)g_csrc[p0 + i + 4] * HID + c);
        if (i + 5 < n) q3 = *(const uint2*)(fsh + (size_t)g_csrc[p0 + i + 5] * HID + c);

        float t0, t1;
        t0 = f0.x + fd4.x; t0 = t0 > 0.f ? t0 : 0.2f * t0;
        t1 = f1.x + fd4.x; t1 = t1 > 0.f ? t1 : 0.2f * t1;
        float pd0 = t0 * a4.x, pd1 = t1 * a4.x;
        t0 = f0.y + fd4.y; t0 = t0 > 0.f ? t0 : 0.2f * t0;
        t1 = f1.y + fd4.y; t1 = t1 > 0.f ? t1 : 0.2f * t1;
        pd0 += t0 * a4.y; pd1 += t1 * a4.y;
        t0 = f0.z + fd4.z; t0 = t0 > 0.f ? t0 : 0.2f * t0;
        t1 = f1.z + fd4.z; t1 = t1 > 0.f ? t1 : 0.2f * t1;
        pd0 += t0 * a4.z; pd1 += t1 * a4.z;
        t0 = f0.w + fd4.w; t0 = t0 > 0.f ? t0 : 0.2f * t0;
        t1 = f1.w + fd4.w; t1 = t1 > 0.f ? t1 : 0.2f * t1;
        pd0 += t0 * a4.w; pd1 += t1 * a4.w;

        pd0 += __shfl_xor_sync(0xffffffffu, pd0, 1);
        pd1 += __shfl_xor_sync(0xffffffffu, pd1, 1);
        pd0 += __shfl_xor_sync(0xffffffffu, pd0, 2);
        pd1 += __shfl_xor_sync(0xffffffffu, pd1, 2);
        pd0 += __shfl_xor_sync(0xffffffffu, pd0, 4);
        pd1 += __shfl_xor_sync(0xffffffffu, pd1, 4);

        float w0 = __expf(pd0);
        float w1 = __expf(pd1);
        ssum += w0 + w1;
        acc.x += w0 * f0.x + w1 * f1.x;
        acc.y += w0 * f0.y + w1 * f1.y;
        acc.z += w0 * f0.z + w1 * f1.z;
        acc.w += w0 * f0.w + w1 * f1.w;
    }
    if (i < n) {
        float4 f = h4_to_f4(q0);
        float t;
        t = f.x + fd4.x; t = t > 0.f ? t : 0.2f * t; float pd = t * a4.x;
        t = f.y + fd4.y; t = t > 0.f ? t : 0.2f * t; pd += t * a4.y;
        t = f.z + fd4.z; t = t > 0.f ? t : 0.2f * t; pd += t * a4.z;
        t = f.w + fd4.w; t = t > 0.f ? t : 0.2f * t; pd += t * a4.w;
        pd += __shfl_xor_sync(0xffffffffu, pd, 1);
        pd += __shfl_xor_sync(0xffffffffu, pd, 2);
        pd += __shfl_xor_sync(0xffffffffu, pd, 4);
        float w = __expf(pd);
        ssum += w;
        acc.x += w * f.x; acc.y += w * f.y; acc.z += w * f.z; acc.w += w * f.w;
    }

    float inv = 1.f / ssum;
    float x0 = acc.x * inv + 2.f * h4.x;
    float x1 = acc.y * inv + 2.f * h4.y;
    float x2 = acc.z * inv + 2.f * h4.z;
    float x3 = acc.w * inv + 2.f * h4.w;
    float s1 = x0 + x1 + x2 + x3;
#pragma unroll
    for (int d = 16; d; d >>= 1) s1 += __shfl_xor_sync(0xffffffffu, s1, d);
    float mean = s1 * (1.f / 128.f);
    float d0 = x0 - mean, d1 = x1 - mean, d2 = x2 - mean, d3 = x3 - mean;
    float s2 = d0 * d0 + d1 * d1 + d2 * d2 + d3 * d3;
#pragma unroll
    for (int d = 16; d; d >>= 1) s2 += __shfl_xor_sync(0xffffffffu, s2, d);
    float rstd = rsqrtf(s2 * (1.f / 128.f) + 1e-5f);
    float4 g4 = *(const float4*)(lng + c);
    float4 b4 = *(const float4*)(lnb + c);
    float y0 = fmaxf(d0 * rstd * g4.x + b4.x, 0.f);
    float y1 = fmaxf(d1 * rstd * g4.y + b4.y, 0.f);
    float y2 = fmaxf(d2 * rstd * g4.z + b4.z, 0.f);
    float y3 = fmaxf(d3 * rstd * g4.w + b4.w, 0.f);
    *(float4*)(h_out + (size_t)node * HID + c) = make_float4(y0, y1, y2, y3);
}

// ---------------- mean pool over nodes ----------------
__global__ void pool_kernel(const float* __restrict__ h) {
    int col = threadIdx.x;
    int r0 = blockIdx.x * 512;
    int r1 = r0 + 512; if (r1 > N_NODES) r1 = N_NODES;
    float s = 0.f;
    for (int r = r0; r < r1; r++) s += h[(size_t)r * HID + col];
    atomicAdd(&g_pool[col], s);
}

// ---------------- graph head ----------------
__global__ void head_kernel(
    const float* __restrict__ gf, const float* __restrict__ W_g, const float* __restrict__ b_g,
    const float* __restrict__ W_f1, const float* __restrict__ b_f1,
    const float* __restrict__ W_f2, const float* __restrict__ b_f2,
    float* __restrict__ emb)
{
    __shared__ float comb[256];
    __shared__ float r1[128];
    int t = threadIdx.x;
    float gh = b_g[t];
    for (int k = 0; k < GRAPH_DIM; k++) gh += gf[k] * W_g[k * HID + t];
    comb[128 + t] = gh;
    comb[t] = g_pool[t] * (1.f / (float)N_NODES);
    __syncthreads();
    float f1 = b_f1[t];
    for (int k = 0; k < 256; k++) f1 += comb[k] * W_f1[k * HID + t];
    r1[t] = fmaxf(f1, 0.f);
    __syncthreads();
    float f2 = b_f2[t];
    for (int k = 0; k < 128; k++) f2 += r1[k] * W_f2[k * HID + t];
    emb[t] = f2;
}

// ---------------- launch ----------------
extern "C" void kernel_launch(void* const* d_in, const int* in_sizes, int n_in,
                              void* d_out, int out_size)
{
    const float* node_feats  = (const float*)d_in[0];
    const float* graph_feats = (const float*)d_in[1];
    const int*   src         = (const int*)d_in[2];
    const int*   dst         = (const int*)d_in[3];
    const float* W_in  = (const float*)d_in[4];
    const float* b_in  = (const float*)d_in[5];
    const float* W_g   = (const float*)d_in[6];
    const float* b_g   = (const float*)d_in[7];
    const float* W_src = (const float*)d_in[8];
    const float* b_src = (const float*)d_in[9];
    const float* W_dst = (const float*)d_in[10];
    const float* b_dst = (const float*)d_in[11];
    const float* attn  = (const float*)d_in[12];
    const float* ln_g  = (const float*)d_in[13];
    const float* ln_b  = (const float*)d_in[14];
    const float* W_f1  = (const float*)d_in[15];
    const float* b_f1  = (const float*)d_in[16];
    const float* W_f2  = (const float*)d_in[17];
    const float* b_f2  = (const float*)d_in[18];

    int E = in_sizes[2];
    if (E > E_MAX) E = E_MAX;

    float *hA, *hB, *fd, *embS;
    __half* fsh;
    uint4 *whs, *whd, *whin;
    cudaGetSymbolAddress((void**)&hA,   g_hA);
    cudaGetSymbolAddress((void**)&hB,   g_hB);
    cudaGetSymbolAddress((void**)&fsh,  g_fsh);
    cudaGetSymbolAddress((void**)&fd,   g_fd);
    cudaGetSymbolAddress((void**)&embS, g_emb_scratch);
    cudaGetSymbolAddress((void**)&whs,  g_Whs);
    cudaGetSymbolAddress((void**)&whd,  g_Whd);
    cudaGetSymbolAddress((void**)&whin, g_Whin);

    float* out = (float*)d_out;
    float* emb_dst;
    float* hfin;
    long long need = (long long)HID + (long long)N_NODES * HID;
    if ((long long)out_size >= need)            { emb_dst = out;  hfin = out + HID; }
    else if (out_size == N_NODES * HID)         { emb_dst = embS; hfin = out; }
    else                                        { emb_dst = out;  hfin = hB; }

    const int smem128 = 2 * 128 * (64 + 8) * 4;   // 73728 B
    const int smem64  = 2 * 128 * (32 + 8) * 4;   // 40960 B

    static cudaStream_t s2 = nullptr;
    static cudaEvent_t evFork = nullptr, evJoin = nullptr;
    static bool init_done = false;
    if (!init_done) {
        cudaFuncSetAttribute(gemm_tc_kernel<128, true>, cudaFuncAttributeMaxDynamicSharedMemorySize, smem128);
        cudaFuncSetAttribute(gemm_tc_kernel<64, false>, cudaFuncAttributeMaxDynamicSharedMemorySize, smem64);
        cudaStreamCreateWithFlags(&s2, cudaStreamNonBlocking);
        cudaEventCreateWithFlags(&evFork, cudaEventDisableTiming);
        cudaEventCreateWithFlags(&evJoin, cudaEventDisableTiming);
        init_done = true;
    }

    // Fork: CSR build on s2, concurrent with weight prep + GEMMs on main stream
    cudaEventRecord(evFork, 0);
    cudaStreamWaitEvent(s2, evFork, 0);
    zero_kernel<<<(N_NODES + 255) / 256, 256, 0, s2>>>();
    count_kernel<<<(E + 255) / 256, 256, 0, s2>>>(dst, E);
    scan_kernel<<<1, 1024, 0, s2>>>();
    scatter_kernel<<<(E + 255) / 256, 256, 0, s2>>>(src, dst, E);
    cudaEventRecord(evJoin, s2);

    // Weight prep (main stream; GEMMs depend on it)
    {
        int items128 = 128 * 64, blocks128 = (items128 + 255) / 256;
        int items64  = 128 * 32, blocks64  = (items64 + 255) / 256;
        prep_w_kernel<<<blocks64, 256>>>(W_in, (uint32_t*)whin, 64);
        for (int l = 0; l < 3; l++) {
            prep_w_kernel<<<blocks128, 256>>>(W_src + (size_t)l * HID * HID,
                                              (uint32_t*)(whs + (size_t)l * (128 * 72 / 4)), 128);
            prep_w_kernel<<<blocks128, 256>>>(W_dst + (size_t)l * HID * HID,
                                              (uint32_t*)(whd + (size_t)l * (128 * 72 / 4)), 128);
        }
    }

    // Input projection
    {
        dim3 grid((N_NODES + 127) / 128, 1);
        gemm_tc_kernel<64, false><<<grid, 256, smem64>>>(node_feats, whin, b_in, (void*)hA, whin, b_in, hA);
    }

    float* hin = hA;
    for (int l = 0; l < 3; l++) {
        dim3 grid((N_NODES + 127) / 128, 2);
        gemm_tc_kernel<128, true><<<grid, 256, smem128>>>(
            hin,
            whs + (size_t)l * (128 * 72 / 4), b_src + (size_t)l * HID, (void*)fsh,
            whd + (size_t)l * (128 * 72 / 4), b_dst + (size_t)l * HID, fd);
        if (l == 0) cudaStreamWaitEvent(0, evJoin, 0);   // join CSR before first gat
        float* hout = (l == 2) ? hfin : ((hin == hA) ? hB : hA);
        gat_layer_kernel<<<(N_NODES + 7) / 8, 256>>>(
            fsh, fd, hin, attn + (size_t)l * HID,
            ln_g + (size_t)l * HID, ln_b + (size_t)l * HID, hout);
        hin = hout;
    }

    pool_kernel<<<(N_NODES + 511) / 512, 128>>>(hin);
    head_kernel<<<1, 128>>>(graph_feats, W_g, b_g, W_f1, b_f1, W_f2, b_f2, emb_dst);
}

// round 7
// speedup vs baseline: 1.3654x; 1.0299x over previous
#include <cuda_runtime.h>
#include <cuda_fp16.h>
#include <math.h>
#include <stdint.h>

#define N_NODES 50000
#define HID 128
#define NODE_DIM 64
#define GRAPH_DIM 32
#define E_MAX 1700000

// ---------------- scratch (static device globals; no allocation) ----------------
__device__ float  g_hA[N_NODES * HID];
__device__ float  g_hB[N_NODES * HID];
__device__ __half g_fsh[N_NODES * HID];
__device__ float  g_fd[N_NODES * HID];
__device__ int    g_deg[N_NODES];
__device__ int    g_off[N_NODES + 1];
__device__ int    g_cur[N_NODES];
__device__ int    g_csrc[E_MAX];
__device__ float  g_pool[HID];
__device__ float  g_emb_scratch[HID];
// prepped fp16 weights, permuted fragment layout. KP2(128)=72 words/row, KP2(64)=40.
__device__ uint4  g_Whs[3][128 * 72 / 4];
__device__ uint4  g_Whd[3][128 * 72 / 4];
__device__ uint4  g_Whin[128 * 40 / 4];

// ---------------- CSR build ----------------
__global__ void zero_kernel() {
    int i = blockIdx.x * blockDim.x + threadIdx.x;
    if (i < N_NODES) g_deg[i] = 0;
    if (i < HID) g_pool[i] = 0.f;
}

__global__ void count_kernel(const int* __restrict__ dst, int E) {
    int e = blockIdx.x * blockDim.x + threadIdx.x;
    if (e < E) atomicAdd(&g_deg[dst[e]], 1);
}

__global__ void scan_kernel() {
    __shared__ int sums[1024];
    const int CH = (N_NODES + 1023) / 1024;
    int t = threadIdx.x;
    int st = t * CH;
    int en = st + CH; if (en > N_NODES) en = N_NODES;
    if (st > N_NODES) st = N_NODES;
    int s = 0;
    for (int i = st; i < en; i++) s += g_deg[i];
    sums[t] = s;
    __syncthreads();
    for (int d = 1; d < 1024; d <<= 1) {
        int v = (t >= d) ? sums[t - d] : 0;
        __syncthreads();
        sums[t] += v;
        __syncthreads();
    }
    int run = (t == 0) ? 0 : sums[t - 1];
    for (int i = st; i < en; i++) {
        g_off[i] = run;
        g_cur[i] = run;
        run += g_deg[i];
    }
    if (t == 1023) g_off[N_NODES] = sums[1023];
}

__global__ void scatter_kernel(const int* __restrict__ src, const int* __restrict__ dst, int E) {
    int e = blockIdx.x * blockDim.x + threadIdx.x;
    if (e < E) {
        int d = dst[e];
        int pos = atomicAdd(&g_cur[d], 1);
        g_csrc[pos] = src[e];
    }
}

// ---------------- weight prep (all 7 matrices in one launch) ----------------
// word layout: out[n*KP2 + (k>>4)*8 + o(u)], u=(k&15)>>1, o(u)=(u&3)*2+(u>>2)
__global__ void prep_w_all_kernel(const float* __restrict__ W_in,
                                  const float* __restrict__ W_src,
                                  const float* __restrict__ W_dst,
                                  uint32_t* __restrict__ o_in,
                                  uint32_t* __restrict__ o_src,
                                  uint32_t* __restrict__ o_dst) {
    int which = blockIdx.y;                 // 0: W_in, 1-3: W_src[l], 4-6: W_dst[l]
    const float* W; uint32_t* out; int K;
    if (which == 0)      { W = W_in; out = o_in; K = 64; }
    else if (which <= 3) { int l = which - 1; W = W_src + (size_t)l * HID * HID; out = o_src + (size_t)l * (128 * 72); K = 128; }
    else                 { int l = which - 4; W = W_dst + (size_t)l * HID * HID; out = o_dst + (size_t)l * (128 * 72); K = 128; }
    int half_k = K >> 1;
    int idx = blockIdx.x * blockDim.x + threadIdx.x;
    if (idx >= 128 * half_k) return;
    int n = idx / half_k;
    int k = (idx % half_k) * 2;
    float x = W[(size_t)k * HID + n];
    float y = W[(size_t)(k + 1) * HID + n];
    int KP2 = half_k + 8;
    int uu = (k & 15) >> 1;
    int o = (uu & 3) * 2 + (uu >> 2);
    __half2 h = __floats2half2_rn(x, y);
    out[n * KP2 + (k >> 4) * 8 + o] = *(uint32_t*)&h;
}

// ---------------- fp16 tensor-core GEMM (m16n8k16, fp32 accum) ----------------
__device__ __forceinline__ void mma_f16(float* c, const uint32_t* a, const uint32_t* b) {
    asm volatile(
        "mma.sync.aligned.m16n8k16.row.col.f32.f16.f16.f32 "
        "{%0,%1,%2,%3}, {%4,%5,%6,%7}, {%8,%9}, {%0,%1,%2,%3};"
        : "+f"(c[0]), "+f"(c[1]), "+f"(c[2]), "+f"(c[3])
        : "r"(a[0]), "r"(a[1]), "r"(a[2]), "r"(a[3]), "r"(b[0]), "r"(b[1]));
}

template <int K, bool HALF1>
__global__ void __launch_bounds__(256) gemm_tc_kernel(
    const float* __restrict__ A,
    const uint4* __restrict__ Wh1, const float* __restrict__ b1, void* __restrict__ C1v,
    const uint4* __restrict__ Wh2, const float* __restrict__ b2, float* __restrict__ C2)
{
    constexpr int KP2 = K / 2 + 8;
    extern __shared__ uint32_t smem_u[];
    uint32_t* sA = smem_u;
    uint32_t* sB = smem_u + 128 * KP2;

    const uint4* Wh; const float* bias;
    bool halfOut = HALF1 && (blockIdx.y == 0);
    if (blockIdx.y == 0) { Wh = Wh1; bias = b1; }
    else                 { Wh = Wh2; bias = b2; }

    int row0 = blockIdx.x * 128;
    int tid = threadIdx.x;

    const int o0tab[4] = {0, 4, 1, 5};
    const int o1tab[4] = {2, 6, 3, 7};
    for (int i = tid; i < 128 * (K / 4); i += 256) {
        int r = i / (K / 4);
        int q = i % (K / 4);
        int row = row0 + r;
        float4 v = make_float4(0.f, 0.f, 0.f, 0.f);
        if (row < N_NODES) v = *(const float4*)(A + (size_t)row * K + q * 4);
        int base = r * KP2 + (q >> 2) * 8;
        __half2 h01 = __floats2half2_rn(v.x, v.y);
        __half2 h23 = __floats2half2_rn(v.z, v.w);
        sA[base + o0tab[q & 3]] = *(uint32_t*)&h01;
        sA[base + o1tab[q & 3]] = *(uint32_t*)&h23;
    }
    {
        uint4* dst = (uint4*)sB;
        for (int i = tid; i < 128 * KP2 / 4; i += 256) dst[i] = Wh[i];
    }
    __syncthreads();

    int warp = tid >> 5;
    int lane = tid & 31;
    int mwarp = warp >> 1;
    int nwarp = warp & 1;
    int g = lane >> 2;
    int tg = lane & 3;

    float acc[2][8][4];
#pragma unroll
    for (int t = 0; t < 2; t++)
#pragma unroll
        for (int j = 0; j < 8; j++) { acc[t][j][0] = acc[t][j][1] = acc[t][j][2] = acc[t][j][3] = 0.f; }

    int rb = mwarp * 32 + g;
#pragma unroll
    for (int ks = 0; ks < K / 16; ks++) {
        int kk = ks * 8 + tg * 2;
        uint2 a00 = *(const uint2*)(sA + (rb)      * KP2 + kk);
        uint2 a01 = *(const uint2*)(sA + (rb + 8)  * KP2 + kk);
        uint2 a10 = *(const uint2*)(sA + (rb + 16) * KP2 + kk);
        uint2 a11 = *(const uint2*)(sA + (rb + 24) * KP2 + kk);
        uint32_t afr0[4] = {a00.x, a01.x, a00.y, a01.y};
        uint32_t afr1[4] = {a10.x, a11.x, a10.y, a11.y};
        uint32_t bfr[8][2];
#pragma unroll
        for (int j = 0; j < 8; j++) {
            int n0 = nwarp * 64 + j * 8 + g;
            uint2 b = *(const uint2*)(sB + n0 * KP2 + kk);
            bfr[j][0] = b.x; bfr[j][1] = b.y;
        }
#pragma unroll
        for (int j = 0; j < 8; j++) mma_f16(acc[0][j], afr0, bfr[j]);
#pragma unroll
        for (int j = 0; j < 8; j++) mma_f16(acc[1][j], afr1, bfr[j]);
    }

#pragma unroll
    for (int t = 0; t < 2; t++) {
        int rbase = row0 + mwarp * 32 + t * 16 + g;
#pragma unroll
        for (int j = 0; j < 8; j++) {
            int col = nwarp * 64 + j * 8 + tg * 2;
            float bx = __ldg(bias + col);
            float by = __ldg(bias + col + 1);
            float v0x = acc[t][j][0] + bx, v0y = acc[t][j][1] + by;
            float v1x = acc[t][j][2] + bx, v1y = acc[t][j][3] + by;
            if (halfOut) {
                __half* C = (__half*)C1v;
                if (rbase < N_NODES)
                    *(__half2*)(C + (size_t)rbase * HID + col) = __floats2half2_rn(v0x, v0y);
                if (rbase + 8 < N_NODES)
                    *(__half2*)(C + (size_t)(rbase + 8) * HID + col) = __floats2half2_rn(v1x, v1y);
            } else {
                float* C = (blockIdx.y == 0) ? (float*)C1v : C2;
                if (rbase < N_NODES)
                    *(float2*)(C + (size_t)rbase * HID + col) = make_float2(v0x, v0y);
                if (rbase + 8 < N_NODES)
                    *(float2*)(C + (size_t)(rbase + 8) * HID + col) = make_float2(v1x, v1y);
            }
        }
    }
}

// ---------------- GATv2 layer: warp/node, half-warp per edge (2 edges per warp-instr) ------
// Lanes 0-15 process even edges, 16-31 odd edges. Each lane owns 8 columns (uint4 fp16 gather).
__global__ void __launch_bounds__(256) gat_layer_kernel(
    const __half* __restrict__ fsh, const float* __restrict__ fd,
    const float* __restrict__ h_in, const float* __restrict__ attn,
    const float* __restrict__ lng, const float* __restrict__ lnb,
    float* __restrict__ h_out)
{
    int warp = (blockIdx.x * blockDim.x + threadIdx.x) >> 5;
    if (warp >= N_NODES) return;
    int node = warp;
    int lane = threadIdx.x & 31;
    int hl  = lane & 15;          // half-lane: column group
    int sub = lane >> 4;          // 0: even edges, 1: odd edges
    int c = hl * 8;               // 8 columns per lane; head = hl>>2 (4 lanes per head)
    unsigned hmask = sub ? 0xffff0000u : 0x0000ffffu;

    float fd8[8], a8[8];
    {
        float4 u = *(const float4*)(fd + (size_t)node * HID + c);
        float4 v = *(const float4*)(fd + (size_t)node * HID + c + 4);
        fd8[0]=u.x; fd8[1]=u.y; fd8[2]=u.z; fd8[3]=u.w;
        fd8[4]=v.x; fd8[5]=v.y; fd8[6]=v.z; fd8[7]=v.w;
        float4 au = *(const float4*)(attn + c);
        float4 av = *(const float4*)(attn + c + 4);
        a8[0]=au.x; a8[1]=au.y; a8[2]=au.z; a8[3]=au.w;
        a8[4]=av.x; a8[5]=av.y; a8[6]=av.z; a8[7]=av.w;
    }

    int p0 = g_off[node];
    int n  = g_off[node + 1] - p0;   // >= 1

    float ssum = 0.f;
    float acc[8];
#pragma unroll
    for (int j = 0; j < 8; j++) acc[j] = 0.f;

    // prefetch depth 2 per half-warp
    uint4 q0 = make_uint4(0,0,0,0), q1 = q0;
    if (sub     < n) q0 = *(const uint4*)(fsh + (size_t)g_csrc[p0 + sub]     * HID + c);
    if (sub + 2 < n) q1 = *(const uint4*)(fsh + (size_t)g_csrc[p0 + sub + 2] * HID + c);

    for (int i = sub; i < n; i += 2) {
        uint4 q = q0; q0 = q1;
        int inx = i + 4;
        if (inx < n) q1 = *(const uint4*)(fsh + (size_t)g_csrc[p0 + inx] * HID + c);

        float f[8];
        {
            __half2* hp = (__half2*)&q;
#pragma unroll
            for (int j = 0; j < 4; j++) {
                float2 t2 = __half22float2(hp[j]);
                f[2 * j] = t2.x; f[2 * j + 1] = t2.y;
            }
        }
        float pd = 0.f;
#pragma unroll
        for (int j = 0; j < 8; j++) {
            float t = f[j] + fd8[j];
            t = t > 0.f ? t : 0.2f * t;
            pd += t * a8[j];
        }
        // reduce over the 4 lanes of this head (xor 1,2 stays within half-warp)
        pd += __shfl_xor_sync(hmask, pd, 1);
        pd += __shfl_xor_sync(hmask, pd, 2);
        float w = __expf(pd);
        ssum += w;
#pragma unroll
        for (int j = 0; j < 8; j++) acc[j] += w * f[j];
    }

    __syncwarp();
    // combine the two half-warps (paired lanes own the same columns/head)
    ssum += __shfl_xor_sync(0xffffffffu, ssum, 16);
#pragma unroll
    for (int j = 0; j < 8; j++) acc[j] += __shfl_xor_sync(0xffffffffu, acc[j], 16);

    float inv = 1.f / ssum;
    float x[8];
    {
        float4 hu = *(const float4*)(h_in + (size_t)node * HID + c);
        float4 hv = *(const float4*)(h_in + (size_t)node * HID + c + 4);
        x[0] = acc[0] * inv + 2.f * hu.x;
        x[1] = acc[1] * inv + 2.f * hu.y;
        x[2] = acc[2] * inv + 2.f * hu.z;
        x[3] = acc[3] * inv + 2.f * hu.w;
        x[4] = acc[4] * inv + 2.f * hv.x;
        x[5] = acc[5] * inv + 2.f * hv.y;
        x[6] = acc[6] * inv + 2.f * hv.z;
        x[7] = acc[7] * inv + 2.f * hv.w;
    }
    float s1 = 0.f;
#pragma unroll
    for (int j = 0; j < 8; j++) s1 += x[j];
#pragma unroll
    for (int d = 8; d; d >>= 1) s1 += __shfl_xor_sync(0xffffffffu, s1, d);  // over 16-lane group
    float mean = s1 * (1.f / 128.f);
    float dv[8];
    float s2 = 0.f;
#pragma unroll
    for (int j = 0; j < 8; j++) { dv[j] = x[j] - mean; s2 += dv[j] * dv[j]; }
#pragma unroll
    for (int d = 8; d; d >>= 1) s2 += __shfl_xor_sync(0xffffffffu, s2, d);
    float rstd = rsqrtf(s2 * (1.f / 128.f) + 1e-5f);

    if (sub == 0) {
        float4 gu = *(const float4*)(lng + c);
        float4 gv = *(const float4*)(lng + c + 4);
        float4 bu = *(const float4*)(lnb + c);
        float4 bv = *(const float4*)(lnb + c + 4);
        float4 y0, y1;
        y0.x = fmaxf(dv[0] * rstd * gu.x + bu.x, 0.f);
        y0.y = fmaxf(dv[1] * rstd * gu.y + bu.y, 0.f);
        y0.z = fmaxf(dv[2] * rstd * gu.z + bu.z, 0.f);
        y0.w = fmaxf(dv[3] * rstd * gu.w + bu.w, 0.f);
        y1.x = fmaxf(dv[4] * rstd * gv.x + bv.x, 0.f);
        y1.y = fmaxf(dv[5] * rstd * gv.y + bv.y, 0.f);
        y1.z = fmaxf(dv[6] * rstd * gv.z + bv.z, 0.f);
        y1.w = fmaxf(dv[7] * rstd * gv.w + bv.w, 0.f);
        *(float4*)(h_out + (size_t)node * HID + c)     = y0;
        *(float4*)(h_out + (size_t)node * HID + c + 4) = y1;
    }
}

// ---------------- mean pool over nodes ----------------
__global__ void pool_kernel(const float* __restrict__ h) {
    int col = threadIdx.x;
    int r0 = blockIdx.x * 512;
    int r1 = r0 + 512; if (r1 > N_NODES) r1 = N_NODES;
    float s = 0.f;
    for (int r = r0; r < r1; r++) s += h[(size_t)r * HID + col];
    atomicAdd(&g_pool[col], s);
}

// ---------------- graph head ----------------
__global__ void head_kernel(
    const float* __restrict__ gf, const float* __restrict__ W_g, const float* __restrict__ b_g,
    const float* __restrict__ W_f1, const float* __restrict__ b_f1,
    const float* __restrict__ W_f2, const float* __restrict__ b_f2,
    float* __restrict__ emb)
{
    __shared__ float comb[256];
    __shared__ float r1[128];
    int t = threadIdx.x;
    float gh = b_g[t];
    for (int k = 0; k < GRAPH_DIM; k++) gh += gf[k] * W_g[k * HID + t];
    comb[128 + t] = gh;
    comb[t] = g_pool[t] * (1.f / (float)N_NODES);
    __syncthreads();
    float f1 = b_f1[t];
    for (int k = 0; k < 256; k++) f1 += comb[k] * W_f1[k * HID + t];
    r1[t] = fmaxf(f1, 0.f);
    __syncthreads();
    float f2 = b_f2[t];
    for (int k = 0; k < 128; k++) f2 += r1[k] * W_f2[k * HID + t];
    emb[t] = f2;
}

// ---------------- launch ----------------
extern "C" void kernel_launch(void* const* d_in, const int* in_sizes, int n_in,
                              void* d_out, int out_size)
{
    const float* node_feats  = (const float*)d_in[0];
    const float* graph_feats = (const float*)d_in[1];
    const int*   src         = (const int*)d_in[2];
    const int*   dst         = (const int*)d_in[3];
    const float* W_in  = (const float*)d_in[4];
    const float* b_in  = (const float*)d_in[5];
    const float* W_g   = (const float*)d_in[6];
    const float* b_g   = (const float*)d_in[7];
    const float* W_src = (const float*)d_in[8];
    const float* b_src = (const float*)d_in[9];
    const float* W_dst = (const float*)d_in[10];
    const float* b_dst = (const float*)d_in[11];
    const float* attn  = (const float*)d_in[12];
    const float* ln_g  = (const float*)d_in[13];
    const float* ln_b  = (const float*)d_in[14];
    const float* W_f1  = (const float*)d_in[15];
    const float* b_f1  = (const float*)d_in[16];
    const float* W_f2  = (const float*)d_in[17];
    const float* b_f2  = (const float*)d_in[18];

    int E = in_sizes[2];
    if (E > E_MAX) E = E_MAX;

    float *hA, *hB, *fd, *embS;
    __half* fsh;
    uint4 *whs, *whd, *whin;
    cudaGetSymbolAddress((void**)&hA,   g_hA);
    cudaGetSymbolAddress((void**)&hB,   g_hB);
    cudaGetSymbolAddress((void**)&fsh,  g_fsh);
    cudaGetSymbolAddress((void**)&fd,   g_fd);
    cudaGetSymbolAddress((void**)&embS, g_emb_scratch);
    cudaGetSymbolAddress((void**)&whs,  g_Whs);
    cudaGetSymbolAddress((void**)&whd,  g_Whd);
    cudaGetSymbolAddress((void**)&whin, g_Whin);

    float* out = (float*)d_out;
    float* emb_dst;
    float* hfin;
    long long need = (long long)HID + (long long)N_NODES * HID;
    if ((long long)out_size >= need)            { emb_dst = out;  hfin = out + HID; }
    else if (out_size == N_NODES * HID)         { emb_dst = embS; hfin = out; }
    else                                        { emb_dst = out;  hfin = hB; }

    const int smem128 = 2 * 128 * (64 + 8) * 4;   // 73728 B
    const int smem64  = 2 * 128 * (32 + 8) * 4;   // 40960 B

    static cudaStream_t s2 = nullptr;
    static cudaEvent_t evFork = nullptr, evJoin = nullptr;
    static bool init_done = false;
    if (!init_done) {
        cudaFuncSetAttribute(gemm_tc_kernel<128, true>, cudaFuncAttributeMaxDynamicSharedMemorySize, smem128);
        cudaFuncSetAttribute(gemm_tc_kernel<64, false>, cudaFuncAttributeMaxDynamicSharedMemorySize, smem64);
        cudaStreamCreateWithFlags(&s2, cudaStreamNonBlocking);
        cudaEventCreateWithFlags(&evFork, cudaEventDisableTiming);
        cudaEventCreateWithFlags(&evJoin, cudaEventDisableTiming);
        init_done = true;
    }

    // Fork: CSR build on s2, concurrent with weight prep + GEMMs on main stream
    cudaEventRecord(evFork, 0);
    cudaStreamWaitEvent(s2, evFork, 0);
    zero_kernel<<<(N_NODES + 255) / 256, 256, 0, s2>>>();
    count_kernel<<<(E + 255) / 256, 256, 0, s2>>>(dst, E);
    scan_kernel<<<1, 1024, 0, s2>>>();
    scatter_kernel<<<(E + 255) / 256, 256, 0, s2>>>(src, dst, E);
    cudaEventRecord(evJoin, s2);

    // Weight prep: all 7 matrices in one launch
    {
        dim3 grid((128 * 64 + 255) / 256, 7);
        prep_w_all_kernel<<<grid, 256>>>(W_in, W_src, W_dst,
                                         (uint32_t*)whin, (uint32_t*)whs, (uint32_t*)whd);
    }

    // Input projection
    {
        dim3 grid((N_NODES + 127) / 128, 1);
        gemm_tc_kernel<64, false><<<grid, 256, smem64>>>(node_feats, whin, b_in, (void*)hA, whin, b_in, hA);
    }

    float* hin = hA;
    for (int l = 0; l < 3; l++) {
        dim3 grid((N_NODES + 127) / 128, 2);
        gemm_tc_kernel<128, true><<<grid, 256, smem128>>>(
            hin,
            whs + (size_t)l * (128 * 72 / 4), b_src + (size_t)l * HID, (void*)fsh,
            whd + (size_t)l * (128 * 72 / 4), b_dst + (size_t)l * HID, fd);
        if (l == 0) cudaStreamWaitEvent(0, evJoin, 0);   // join CSR before first gat
        float* hout = (l == 2) ? hfin : ((hin == hA) ? hB : hA);
        gat_layer_kernel<<<(N_NODES + 7) / 8, 256>>>(
            fsh, fd, hin, attn + (size_t)l * HID,
            ln_g + (size_t)l * HID, ln_b + (size_t)l * HID, hout);
        hin = hout;
    }

    pool_kernel<<<(N_NODES + 511) / 512, 128>>>(hin);
    head_kernel<<<1, 128>>>(graph_feats, W_g, b_g, W_f1, b_f1, W_f2, b_f2, emb_dst);
}